// round 13
// baseline (speedup 1.0000x reference)
#include <cuda_runtime.h>
#include <cuda_fp16.h>
#include <stdint.h>

// 3-kernel pipeline (single stream):
//  1) gather_kernel : temp fp32 -> g_qkv[win][qkv][t][d] fp16; Q pre-scaled by SCALE*log2e
//  2) attn_kernel   : streaming no-max softmax attention -> g_o16 fp16 (PURE attention,
//                     LePE conv moved out; epilogue = normalize + store only)
//  3) scatter_kernel: g_o16 + LePE(V from g_qkv) -> out (B,C,H,W); conv fused into the
//                     transpose pass where compute pipes were idle (DRAM-bound kernel)

#define SMEM_A 19456   // half[4][64][38]
#define SMEM_B 40960   // sK/sV half[256][40]
#define SMEM_C 76160   // tileC half[32][530] + tileV half[32][10][66]

__device__ __half g_qkv[1024u * 3u * 256u * 32u];  // 48 MB
__device__ __half g_o16[1024u * 256u * 32u];       // 16 MB

__device__ __forceinline__ void ldm4(uint32_t a, uint32_t& r0, uint32_t& r1,
                                     uint32_t& r2, uint32_t& r3) {
    asm volatile("ldmatrix.sync.aligned.m8n8.x4.shared.b16 {%0,%1,%2,%3}, [%4];"
                 : "=r"(r0), "=r"(r1), "=r"(r2), "=r"(r3) : "r"(a));
}
__device__ __forceinline__ void ldm4t(uint32_t a, uint32_t& r0, uint32_t& r1,
                                      uint32_t& r2, uint32_t& r3) {
    asm volatile("ldmatrix.sync.aligned.m8n8.x4.trans.shared.b16 {%0,%1,%2,%3}, [%4];"
                 : "=r"(r0), "=r"(r1), "=r"(r2), "=r"(r3) : "r"(a));
}
// fp32-accumulator MMA (PV + ones-column row sums)
__device__ __forceinline__ void mma16816(float* c,
                                         uint32_t a0, uint32_t a1, uint32_t a2, uint32_t a3,
                                         uint32_t b0, uint32_t b1) {
    asm volatile("mma.sync.aligned.m16n8k16.row.col.f32.f16.f16.f32 "
                 "{%0,%1,%2,%3},{%4,%5,%6,%7},{%8,%9},{%0,%1,%2,%3};"
                 : "+f"(c[0]), "+f"(c[1]), "+f"(c[2]), "+f"(c[3])
                 : "r"(a0), "r"(a1), "r"(a2), "r"(a3), "r"(b0), "r"(b1));
}
// fp16-accumulator MMA (QK): D layout = {col tg2, tg2+1} half2 per lane
__device__ __forceinline__ void mma16816h(uint32_t& d0, uint32_t& d1,
                                          uint32_t a0, uint32_t a1, uint32_t a2, uint32_t a3,
                                          uint32_t b0, uint32_t b1) {
    asm volatile("mma.sync.aligned.m16n8k16.row.col.f16.f16.f16.f16 "
                 "{%0,%1},{%2,%3,%4,%5},{%6,%7},{%0,%1};"
                 : "+r"(d0), "+r"(d1)
                 : "r"(a0), "r"(a1), "r"(a2), "r"(a3), "r"(b0), "r"(b1));
}
__device__ __forceinline__ uint32_t ex2h2(uint32_t x) {
    asm("ex2.approx.f16x2 %0, %1;" : "=r"(x) : "r"(x));
    return x;
}
__device__ __forceinline__ void cpa16(uint32_t dst, const void* src) {
    asm volatile("cp.async.ca.shared.global [%0], [%1], 16;" :: "r"(dst), "l"(src));
}
__device__ __forceinline__ uint32_t ld32h(const __half* p) {
    return *reinterpret_cast<const uint32_t*>(p);
}

// ---------------------------------------------------------------------------
// Kernel 1: gather + layout transform.  grid = 8b*3p*8head*16h4 = 3072
// ---------------------------------------------------------------------------
__global__ void __launch_bounds__(256)
gather_kernel(const float* __restrict__ temp)
{
    extern __shared__ __half tileA[];  // [4 h][64 w][38 c-padded]
    const int bid = blockIdx.x, tid = threadIdx.x;
    const int h16  = bid & 15;
    const int head = (bid >> 4) & 7;
    const int bp   = bid >> 7;          // b*3 + p
    const int p    = bp % 3;
    const int b    = bp / 3;

    const size_t base = ((size_t)bp * 256 + head * 32) * 4096 + (size_t)(h16 * 4) * 64;
    // Q carries SCALE * log2(e) so QK^T lands directly in the exp2 domain
    const float scale = (p == 0) ? (0.17677669529663687f * 1.4426950408889634f) : 1.0f;

#pragma unroll
    for (int j = tid; j < 1024; j += 256) {
        const int w4 = j & 15, h = (j >> 4) & 3, c2 = j >> 6;
        const int c = c2 * 2;
        const float4 va = *reinterpret_cast<const float4*>(
            temp + base + (size_t)c * 4096 + h * 64 + w4 * 4);
        const float4 vb = *reinterpret_cast<const float4*>(
            temp + base + (size_t)(c + 1) * 4096 + h * 64 + w4 * 4);
        const int sb = (h * 64 + w4 * 4) * 38 + c;
        *reinterpret_cast<__half2*>(&tileA[sb])       = __floats2half2_rn(va.x * scale, vb.x * scale);
        *reinterpret_cast<__half2*>(&tileA[sb + 38])  = __floats2half2_rn(va.y * scale, vb.y * scale);
        *reinterpret_cast<__half2*>(&tileA[sb + 76])  = __floats2half2_rn(va.z * scale, vb.z * scale);
        *reinterpret_cast<__half2*>(&tileA[sb + 114]) = __floats2half2_rn(va.w * scale, vb.w * scale);
    }
    __syncthreads();

    // phase 2: 8 lanes per token, uint2 (8B) stores
    const int wb = (b * 8 + head) * 16;
    const int d  = (tid & 7) * 4;
#pragma unroll
    for (int pp = tid >> 3; pp < 256; pp += 32) {
        const int h = pp >> 6, w = pp & 63;
        const int win = wb + (w & 15);
        const int t   = (h16 * 4 + h) * 4 + (w >> 4);
        const int sb  = (h * 64 + w) * 38 + d;
        uint2 val;
        val.x = *reinterpret_cast<const uint32_t*>(&tileA[sb]);
        val.y = *reinterpret_cast<const uint32_t*>(&tileA[sb + 2]);
        *reinterpret_cast<uint2*>(&g_qkv[(((size_t)win * 3 + p) * 256 + t) * 32 + d]) = val;
    }
}

// ---------------------------------------------------------------------------
// Kernel 2: streaming attention (pure).  grid = 1024 windows, 128 thr
// ---------------------------------------------------------------------------
__global__ void __launch_bounds__(128, 4)
attn_kernel()
{
    const int win  = blockIdx.x;
    const int tid  = threadIdx.x;
    const int lane = tid & 31;
    const int wid  = tid >> 5;

    extern __shared__ char smem[];
    __half* sK = reinterpret_cast<__half*>(smem);            // [256][40]
    __half* sV = reinterpret_cast<__half*>(smem + 20480);    // [256][40]

    const uint32_t kb = (uint32_t)__cvta_generic_to_shared(sK);
    const uint32_t vb = (uint32_t)__cvta_generic_to_shared(sV);

    const __half* qkvg = g_qkv + (size_t)win * 3u * 8192u;
    const uint4* srcK = reinterpret_cast<const uint4*>(qkvg + 8192);
    const uint4* srcV = reinterpret_cast<const uint4*>(qkvg + 16384);

    // pipelined staging: 4 commit groups, 64 tokens (256 uint4) each
#pragma unroll
    for (int gr = 0; gr < 4; ++gr) {
#pragma unroll
        for (int rep = 0; rep < 2; ++rep) {
            const int j = gr * 256 + rep * 128 + tid;
            const int t = j >> 2, dd = (j & 3) * 8;
            const uint32_t off = (uint32_t)(t * 40 + dd) * 2;
            cpa16(kb + off, srcK + j);
            cpa16(vb + off, srcV + j);
        }
        asm volatile("cp.async.commit_group;");
    }

    const int g   = lane >> 2;
    const int tg2 = (lane & 3) << 1;

    // Q fragments direct from gmem, overlapped with staging
    uint32_t qf[4][8];
#pragma unroll
    for (int s = 0; s < 4; ++s) {
        const int r0 = (wid * 4 + s) * 16;
        const __half* q0 = qkvg + (r0 + g) * 32 + tg2;
        const __half* q1 = qkvg + (r0 + g + 8) * 32 + tg2;
        qf[s][0] = ld32h(q0);      qf[s][1] = ld32h(q1);
        qf[s][2] = ld32h(q0 + 8);  qf[s][3] = ld32h(q1 + 8);
        qf[s][4] = ld32h(q0 + 16); qf[s][5] = ld32h(q1 + 16);
        qf[s][6] = ld32h(q0 + 24); qf[s][7] = ld32h(q1 + 24);
    }

    // group 0 (tokens 0-63) ready -> start computing
    asm volatile("cp.async.wait_group 3;");
    __syncthreads();

    const int lrow = lane & 15;
    const int lcol = (lane >> 4) << 3;

    // ones-column B fragment: lanes 0-3 own n=0 column (1.0 for all k)
    const uint32_t onesB = ((lane >> 2) == 0) ? 0x3C003C00u : 0u;

    __half* og16 = g_o16 + (size_t)win * 8192;

    // strip pairs; K/V fragments double-buffered across chunks
#pragma unroll
    for (int sp = 0; sp < 2; ++sp) {
        float o[2][4][4];
        float ol[2][4];
#pragma unroll
        for (int u = 0; u < 2; ++u) {
            ol[u][0] = 0.f; ol[u][1] = 0.f; ol[u][2] = 0.f; ol[u][3] = 0.f;
#pragma unroll
            for (int on = 0; on < 4; ++on) {
                o[u][on][0] = 0.f; o[u][on][1] = 0.f;
                o[u][on][2] = 0.f; o[u][on][3] = 0.f;
            }
        }

        uint32_t kf[2][8], vf[2][8];
        ldm4 (kb + (uint32_t)((lrow * 40 + lcol) * 2),        kf[0][0], kf[0][1], kf[0][2], kf[0][3]);
        ldm4 (kb + (uint32_t)((lrow * 40 + 16 + lcol) * 2),   kf[0][4], kf[0][5], kf[0][6], kf[0][7]);
        ldm4t(vb + (uint32_t)((lrow * 40 + lcol) * 2),        vf[0][0], vf[0][1], vf[0][2], vf[0][3]);
        ldm4t(vb + (uint32_t)((lrow * 40 + 16 + lcol) * 2),   vf[0][4], vf[0][5], vf[0][6], vf[0][7]);

#pragma unroll
        for (int kt = 0; kt < 16; ++kt) {
            // progressive staging waits (first pass only)
            if (sp == 0 && kt == 3)  { asm volatile("cp.async.wait_group 2;"); __syncthreads(); }
            if (sp == 0 && kt == 7)  { asm volatile("cp.async.wait_group 1;"); __syncthreads(); }
            if (sp == 0 && kt == 11) { asm volatile("cp.async.wait_group 0;"); __syncthreads(); }

            const int cur = kt & 1;
            const int nxt = cur ^ 1;
            if (kt < 15) {
                const uint32_t rb = (uint32_t)(((kt + 1) * 16 + lrow) * 40) * 2;
                ldm4 (kb + rb + lcol * 2,        kf[nxt][0], kf[nxt][1], kf[nxt][2], kf[nxt][3]);
                ldm4 (kb + rb + (16 + lcol) * 2, kf[nxt][4], kf[nxt][5], kf[nxt][6], kf[nxt][7]);
                ldm4t(vb + rb + lcol * 2,        vf[nxt][0], vf[nxt][1], vf[nxt][2], vf[nxt][3]);
                ldm4t(vb + rb + (16 + lcol) * 2, vf[nxt][4], vf[nxt][5], vf[nxt][6], vf[nxt][7]);
            }

#pragma unroll
            for (int u = 0; u < 2; ++u) {
                const int s = sp * 2 + u;
                uint32_t s0 = 0u, s1 = 0u, s2 = 0u, s3 = 0u;
                mma16816h(s0, s1, qf[s][0], qf[s][1], qf[s][2], qf[s][3], kf[cur][0], kf[cur][2]);
                mma16816h(s0, s1, qf[s][4], qf[s][5], qf[s][6], qf[s][7], kf[cur][4], kf[cur][6]);
                mma16816h(s2, s3, qf[s][0], qf[s][1], qf[s][2], qf[s][3], kf[cur][1], kf[cur][3]);
                mma16816h(s2, s3, qf[s][4], qf[s][5], qf[s][6], qf[s][7], kf[cur][5], kf[cur][7]);

                // exp2 directly on the f16 MMA output (log2 domain; no max)
                const uint32_t p0 = ex2h2(s0);
                const uint32_t p1 = ex2h2(s1);
                const uint32_t p2 = ex2h2(s2);
                const uint32_t p3 = ex2h2(s3);

                mma16816(o[u][0], p0, p1, p2, p3, vf[cur][0], vf[cur][1]);
                mma16816(o[u][1], p0, p1, p2, p3, vf[cur][2], vf[cur][3]);
                mma16816(o[u][2], p0, p1, p2, p3, vf[cur][4], vf[cur][5]);
                mma16816(o[u][3], p0, p1, p2, p3, vf[cur][6], vf[cur][7]);
                mma16816(ol[u], p0, p1, p2, p3, onesB, onesB);
            }
        }

        // epilogue: normalize + store (conv moved to scatter)
#pragma unroll
        for (int u = 0; u < 2; ++u) {
            const int r0 = (wid * 4 + sp * 2 + u) * 16;
            const float l0 = __shfl_sync(0xffffffffu, ol[u][0], lane & 28);
            const float l1 = __shfl_sync(0xffffffffu, ol[u][2], lane & 28);
            const float inv0 = 1.f / l0;
            const float inv1 = 1.f / l1;

#pragma unroll
            for (int on = 0; on < 4; ++on) {
                const int d0 = on * 8 + tg2;
#pragma unroll
                for (int ocp = 0; ocp < 4; ocp += 2) {
                    const int t   = r0 + g + ((ocp & 2) ? 8 : 0);
                    const float inv = (ocp & 2) ? inv1 : inv0;
                    const __half2 r = __floats2half2_rn(o[u][on][ocp] * inv,
                                                        o[u][on][ocp + 1] * inv);
                    *reinterpret_cast<__half2*>(&og16[t * 32 + d0]) = r;
                }
            }
        }
    }
}

// ---------------------------------------------------------------------------
// Kernel 3: scatter + fused LePE conv.  grid = 8(b)*8(head)*8(h8) = 512
// ---------------------------------------------------------------------------
__global__ void __launch_bounds__(256)
scatter_kernel(float* __restrict__ out,
               const float* __restrict__ wgt,
               const float* __restrict__ bias)
{
    extern __shared__ __half smc[];
    __half* tileC = smc;            // [32 c][8 h][64 w]: c-stride 530, h-stride 66
    __half* tileV = smc + 16960;    // [32 c][10 rows][66]: c-stride 660, row-stride 66

    const int bid = blockIdx.x, tid = threadIdx.x;
    const int h8   = bid & 7;
    const int head = (bid >> 3) & 7;
    const int b    = bid >> 6;
    const int h0   = h8 * 8;
    const int lane = tid & 31, wid = tid >> 5;
    const int wb   = (b * 8 + head) * 16;
    const int cbase = head * 32;
    const int d0   = (lane & 15) * 2;
    const int hiL  = lane >> 4;

    // per-thread conv weights/bias for phase 2 (thread owns channel cth)
    const int cth = tid >> 3;       // 0..31
    float w9[9];
#pragma unroll
    for (int k = 0; k < 9; ++k) w9[k] = wgt[(cbase + cth) * 9 + k];
    const float bth = bias[cbase + cth];

    // phase 1a: attention O transpose (shuffle-paired STS.32)
#pragma unroll
    for (int pp = wid; pp < 256; pp += 8) {
        const int p2 = pp * 2 + hiL;
        const int h = p2 >> 6, w = p2 & 63;
        const int win = wb + (w & 15);
        const int t   = (h0 + h) * 4 + (w >> 4);
        const uint32_t mine = *reinterpret_cast<const uint32_t*>(
            &g_o16[((size_t)win * 256 + t) * 32 + d0]);
        const uint32_t other = __shfl_xor_sync(0xffffffffu, mine, 16);
        uint32_t pairv;
        if (hiL == 0) {
            pairv = (mine & 0xFFFFu) | (other << 16);
        } else {
            pairv = (other >> 16) | (mine & 0xFFFF0000u);
        }
        const int c = d0 + hiL;
        const int weven = w & ~1;
        *reinterpret_cast<uint32_t*>(&tileC[c * 530 + h * 66 + weven]) = pairv;
    }

    // phase 1b: V halo tile (rows h0-1 .. h0+8; zero outside image)
#pragma unroll
    for (int pp = wid; pp < 320; pp += 8) {
        const int p2  = pp * 2 + hiL;
        const int row = p2 >> 6;            // 0..9
        const int w   = p2 & 63;
        const int hh  = h0 - 1 + row;
        uint32_t v = 0u;
        if ((unsigned)hh < 64u) {
            const int win = wb + (w & 15);
            const int t   = hh * 4 + (w >> 4);
            v = *reinterpret_cast<const uint32_t*>(
                &g_qkv[(((size_t)win * 3 + 2) * 256 + t) * 32 + d0]);
        }
        tileV[d0 * 660 + row * 66 + w]       = __ushort_as_half((unsigned short)(v & 0xFFFFu));
        tileV[(d0 + 1) * 660 + row * 66 + w] = __ushort_as_half((unsigned short)(v >> 16));
    }
    __syncthreads();

    // phase 2: conv(V) + O, STG.128 coalesced (thread = fixed channel cth, row e)
    const int e = tid & 7;
    const __half* vbase = &tileV[cth * 660 + e * 66];   // row e+dh covers ih-1..ih+1
    const __half* obase = &tileC[cth * 530 + e * 66];
    float* gout = out + ((size_t)b * 256 + cbase + cth) * 4096 + (size_t)(h0 + e) * 64;

#pragma unroll
    for (int w4 = 0; w4 < 16; ++w4) {
        float4 r;
        float* rp = &r.x;
#pragma unroll
        for (int i = 0; i < 4; ++i) {
            const int w = w4 * 4 + i;
            float acc = bth;
#pragma unroll
            for (int dj = 0; dj < 3; ++dj) {
                const int wp = w + (dj - 1) * 16;      // jw +/- 1 within the 64x4 window
                if ((unsigned)wp < 64u) {
#pragma unroll
                    for (int dh = 0; dh < 3; ++dh) {
                        acc = fmaf(w9[dh * 3 + dj],
                                   __half2float(vbase[dh * 66 + wp]), acc);
                    }
                }
            }
            rp[i] = acc + __half2float(obase[w]);
        }
        *reinterpret_cast<float4*>(gout + w4 * 4) = r;
    }
}

// ---------------------------------------------------------------------------
extern "C" void kernel_launch(void* const* d_in, const int* in_sizes, int n_in,
                              void* d_out, int out_size)
{
    (void)in_sizes; (void)n_in; (void)out_size;
    const float* temp = (const float*)d_in[0];
    const float* wgt  = (const float*)d_in[1];
    const float* bias = (const float*)d_in[2];
    float* out = (float*)d_out;

    cudaFuncSetAttribute(gather_kernel,  cudaFuncAttributeMaxDynamicSharedMemorySize, SMEM_A);
    cudaFuncSetAttribute(attn_kernel,    cudaFuncAttributeMaxDynamicSharedMemorySize, SMEM_B);
    cudaFuncSetAttribute(scatter_kernel, cudaFuncAttributeMaxDynamicSharedMemorySize, SMEM_C);

    gather_kernel<<<3072, 256, SMEM_A>>>(temp);
    attn_kernel<<<1024, 128, SMEM_B>>>();
    scatter_kernel<<<512, 256, SMEM_C>>>(out, wgt, bias);
}

// round 14
// speedup vs baseline: 1.0856x; 1.0856x over previous
#include <cuda_runtime.h>
#include <cuda_fp16.h>
#include <stdint.h>

// 3-kernel pipeline (single stream), round-12 structure:
//  1) gather_kernel : temp fp32 -> g_qkv[win][qkv][t][d] fp16; Q pre-scaled by SCALE*log2e
//  2) attn_kernel   : streaming no-max softmax attention + fused LePE -> g_o16 fp16
//                     f16-acc QK MMA; ones-column MMA row-sums; pipelined staging;
//                     NOW 8 warps/CTA, one strip-pair per warp (half the serial path)
//  3) scatter_kernel: g_o16 -> out (B,C,H,W); shuffle-paired STS.32 transpose, STG.128

#define SMEM_A 19456   // half[4][64][38]
#define SMEM_B 42240   // sK/sV half[256][40] + sW2 float2[16][9] + sB2 float2[16]
#define SMEM_C 33920   // half[32][530]  (c-stride 530, h-stride 66)

__device__ __half g_qkv[1024u * 3u * 256u * 32u];  // 48 MB
__device__ __half g_o16[1024u * 256u * 32u];       // 16 MB

__device__ __forceinline__ void ldm4(uint32_t a, uint32_t& r0, uint32_t& r1,
                                     uint32_t& r2, uint32_t& r3) {
    asm volatile("ldmatrix.sync.aligned.m8n8.x4.shared.b16 {%0,%1,%2,%3}, [%4];"
                 : "=r"(r0), "=r"(r1), "=r"(r2), "=r"(r3) : "r"(a));
}
__device__ __forceinline__ void ldm4t(uint32_t a, uint32_t& r0, uint32_t& r1,
                                      uint32_t& r2, uint32_t& r3) {
    asm volatile("ldmatrix.sync.aligned.m8n8.x4.trans.shared.b16 {%0,%1,%2,%3}, [%4];"
                 : "=r"(r0), "=r"(r1), "=r"(r2), "=r"(r3) : "r"(a));
}
// fp32-accumulator MMA (PV + ones-column row sums)
__device__ __forceinline__ void mma16816(float* c,
                                         uint32_t a0, uint32_t a1, uint32_t a2, uint32_t a3,
                                         uint32_t b0, uint32_t b1) {
    asm volatile("mma.sync.aligned.m16n8k16.row.col.f32.f16.f16.f32 "
                 "{%0,%1,%2,%3},{%4,%5,%6,%7},{%8,%9},{%0,%1,%2,%3};"
                 : "+f"(c[0]), "+f"(c[1]), "+f"(c[2]), "+f"(c[3])
                 : "r"(a0), "r"(a1), "r"(a2), "r"(a3), "r"(b0), "r"(b1));
}
// fp16-accumulator MMA (QK): D layout = {col tg2, tg2+1} half2 per lane
__device__ __forceinline__ void mma16816h(uint32_t& d0, uint32_t& d1,
                                          uint32_t a0, uint32_t a1, uint32_t a2, uint32_t a3,
                                          uint32_t b0, uint32_t b1) {
    asm volatile("mma.sync.aligned.m16n8k16.row.col.f16.f16.f16.f16 "
                 "{%0,%1},{%2,%3,%4,%5},{%6,%7},{%0,%1};"
                 : "+r"(d0), "+r"(d1)
                 : "r"(a0), "r"(a1), "r"(a2), "r"(a3), "r"(b0), "r"(b1));
}
__device__ __forceinline__ uint32_t ex2h2(uint32_t x) {
    asm("ex2.approx.f16x2 %0, %1;" : "=r"(x) : "r"(x));
    return x;
}
__device__ __forceinline__ void cpa16(uint32_t dst, const void* src) {
    asm volatile("cp.async.ca.shared.global [%0], [%1], 16;" :: "r"(dst), "l"(src));
}
__device__ __forceinline__ uint32_t ld32h(const __half* p) {
    return *reinterpret_cast<const uint32_t*>(p);
}

// ---------------------------------------------------------------------------
// Kernel 1: gather + layout transform.  grid = 8b*3p*8head*16h4 = 3072
// ---------------------------------------------------------------------------
__global__ void __launch_bounds__(256)
gather_kernel(const float* __restrict__ temp)
{
    extern __shared__ __half tileA[];  // [4 h][64 w][38 c-padded]
    const int bid = blockIdx.x, tid = threadIdx.x;
    const int h16  = bid & 15;
    const int head = (bid >> 4) & 7;
    const int bp   = bid >> 7;          // b*3 + p
    const int p    = bp % 3;
    const int b    = bp / 3;

    const size_t base = ((size_t)bp * 256 + head * 32) * 4096 + (size_t)(h16 * 4) * 64;
    // Q carries SCALE * log2(e) so QK^T lands directly in the exp2 domain
    const float scale = (p == 0) ? (0.17677669529663687f * 1.4426950408889634f) : 1.0f;

#pragma unroll
    for (int j = tid; j < 1024; j += 256) {
        const int w4 = j & 15, h = (j >> 4) & 3, c2 = j >> 6;
        const int c = c2 * 2;
        const float4 va = *reinterpret_cast<const float4*>(
            temp + base + (size_t)c * 4096 + h * 64 + w4 * 4);
        const float4 vb = *reinterpret_cast<const float4*>(
            temp + base + (size_t)(c + 1) * 4096 + h * 64 + w4 * 4);
        const int sb = (h * 64 + w4 * 4) * 38 + c;
        *reinterpret_cast<__half2*>(&tileA[sb])       = __floats2half2_rn(va.x * scale, vb.x * scale);
        *reinterpret_cast<__half2*>(&tileA[sb + 38])  = __floats2half2_rn(va.y * scale, vb.y * scale);
        *reinterpret_cast<__half2*>(&tileA[sb + 76])  = __floats2half2_rn(va.z * scale, vb.z * scale);
        *reinterpret_cast<__half2*>(&tileA[sb + 114]) = __floats2half2_rn(va.w * scale, vb.w * scale);
    }
    __syncthreads();

    // phase 2: 8 lanes per token, uint2 (8B) stores
    const int wb = (b * 8 + head) * 16;
    const int d  = (tid & 7) * 4;
#pragma unroll
    for (int pp = tid >> 3; pp < 256; pp += 32) {
        const int h = pp >> 6, w = pp & 63;
        const int win = wb + (w & 15);
        const int t   = (h16 * 4 + h) * 4 + (w >> 4);
        const int sb  = (h * 64 + w) * 38 + d;
        uint2 val;
        val.x = *reinterpret_cast<const uint32_t*>(&tileA[sb]);
        val.y = *reinterpret_cast<const uint32_t*>(&tileA[sb + 2]);
        *reinterpret_cast<uint2*>(&g_qkv[(((size_t)win * 3 + p) * 256 + t) * 32 + d]) = val;
    }
}

// ---------------------------------------------------------------------------
// Kernel 2: streaming attention + fused LePE.  grid = 1024 windows, 256 thr
//           8 warps, one strip-pair (32 query rows) per warp
// ---------------------------------------------------------------------------
__global__ void __launch_bounds__(256, 2)
attn_kernel(const float* __restrict__ wgt, const float* __restrict__ bias)
{
    const int win  = blockIdx.x;
    const int tid  = threadIdx.x;
    const int lane = tid & 31;
    const int wid  = tid >> 5;          // 0..7

    extern __shared__ char smem[];
    __half* sK  = reinterpret_cast<__half*>(smem);            // [256][40]
    __half* sV  = reinterpret_cast<__half*>(smem + 20480);    // [256][40]
    float2* sW2 = reinterpret_cast<float2*>(smem + 40960);    // [16 chpair][9 tap]
    float2* sB2 = reinterpret_cast<float2*>(smem + 42112);    // [16]

    const int head  = (win >> 4) & 7;
    const int cbase = head * 32;

    const uint32_t kb = (uint32_t)__cvta_generic_to_shared(sK);
    const uint32_t vb = (uint32_t)__cvta_generic_to_shared(sV);

    const __half* qkvg = g_qkv + (size_t)win * 3u * 8192u;
    const uint4* srcK = reinterpret_cast<const uint4*>(qkvg + 8192);
    const uint4* srcV = reinterpret_cast<const uint4*>(qkvg + 16384);

    // pipelined staging: 4 commit groups of 64 tokens (256 uint4), 1 iter each
#pragma unroll
    for (int gr = 0; gr < 4; ++gr) {
        const int j = gr * 256 + tid;
        const int t = j >> 2, dd = (j & 3) * 8;
        const uint32_t off = (uint32_t)(t * 40 + dd) * 2;
        cpa16(kb + off, srcK + j);
        cpa16(vb + off, srcV + j);
        asm volatile("cp.async.commit_group;");
    }

    // overlap with async window: channel-paired conv weights/bias + Q frags
    if (tid < 144) {
        const int cp = tid / 9, k = tid % 9;
        sW2[tid] = make_float2(wgt[(cbase + 2 * cp) * 9 + k],
                               wgt[(cbase + 2 * cp + 1) * 9 + k]);
    }
    if (tid < 16) sB2[tid] = make_float2(bias[cbase + 2 * tid],
                                         bias[cbase + 2 * tid + 1]);

    const int g   = lane >> 2;
    const int tg2 = (lane & 3) << 1;

    // per-warp Q fragments for its strip pair (rows wid*32 .. wid*32+31)
    uint32_t qf[2][8];
#pragma unroll
    for (int u = 0; u < 2; ++u) {
        const int r0 = (wid * 2 + u) * 16;
        const __half* q0 = qkvg + (r0 + g) * 32 + tg2;
        const __half* q1 = qkvg + (r0 + g + 8) * 32 + tg2;
        qf[u][0] = ld32h(q0);      qf[u][1] = ld32h(q1);
        qf[u][2] = ld32h(q0 + 8);  qf[u][3] = ld32h(q1 + 8);
        qf[u][4] = ld32h(q0 + 16); qf[u][5] = ld32h(q1 + 16);
        qf[u][6] = ld32h(q0 + 24); qf[u][7] = ld32h(q1 + 24);
    }

    // group 0 (tokens 0-63) ready -> start computing
    asm volatile("cp.async.wait_group 3;");
    __syncthreads();

    const int lrow = lane & 15;
    const int lcol = (lane >> 4) << 3;

    // ones-column B fragment: lanes 0-3 own n=0 column (1.0 for all k)
    const uint32_t onesB = ((lane >> 2) == 0) ? 0x3C003C00u : 0u;

    __half* og16 = g_o16 + (size_t)win * 8192;

    float o[2][4][4];
    float ol[2][4];
#pragma unroll
    for (int u = 0; u < 2; ++u) {
        ol[u][0] = 0.f; ol[u][1] = 0.f; ol[u][2] = 0.f; ol[u][3] = 0.f;
#pragma unroll
        for (int on = 0; on < 4; ++on) {
            o[u][on][0] = 0.f; o[u][on][1] = 0.f;
            o[u][on][2] = 0.f; o[u][on][3] = 0.f;
        }
    }

    uint32_t kf[2][8], vf[2][8];
    ldm4 (kb + (uint32_t)((lrow * 40 + lcol) * 2),        kf[0][0], kf[0][1], kf[0][2], kf[0][3]);
    ldm4 (kb + (uint32_t)((lrow * 40 + 16 + lcol) * 2),   kf[0][4], kf[0][5], kf[0][6], kf[0][7]);
    ldm4t(vb + (uint32_t)((lrow * 40 + lcol) * 2),        vf[0][0], vf[0][1], vf[0][2], vf[0][3]);
    ldm4t(vb + (uint32_t)((lrow * 40 + 16 + lcol) * 2),   vf[0][4], vf[0][5], vf[0][6], vf[0][7]);

#pragma unroll
    for (int kt = 0; kt < 16; ++kt) {
        // progressive staging waits; prefetch of chunk kt+1 crosses groups at 3/7/11
        if (kt == 3)  { asm volatile("cp.async.wait_group 2;"); __syncthreads(); }
        if (kt == 7)  { asm volatile("cp.async.wait_group 1;"); __syncthreads(); }
        if (kt == 11) { asm volatile("cp.async.wait_group 0;"); __syncthreads(); }

        const int cur = kt & 1;
        const int nxt = cur ^ 1;
        if (kt < 15) {
            const uint32_t rb = (uint32_t)(((kt + 1) * 16 + lrow) * 40) * 2;
            ldm4 (kb + rb + lcol * 2,        kf[nxt][0], kf[nxt][1], kf[nxt][2], kf[nxt][3]);
            ldm4 (kb + rb + (16 + lcol) * 2, kf[nxt][4], kf[nxt][5], kf[nxt][6], kf[nxt][7]);
            ldm4t(vb + rb + lcol * 2,        vf[nxt][0], vf[nxt][1], vf[nxt][2], vf[nxt][3]);
            ldm4t(vb + rb + (16 + lcol) * 2, vf[nxt][4], vf[nxt][5], vf[nxt][6], vf[nxt][7]);
        }

#pragma unroll
        for (int u = 0; u < 2; ++u) {
            uint32_t s0 = 0u, s1 = 0u, s2 = 0u, s3 = 0u;
            mma16816h(s0, s1, qf[u][0], qf[u][1], qf[u][2], qf[u][3], kf[cur][0], kf[cur][2]);
            mma16816h(s0, s1, qf[u][4], qf[u][5], qf[u][6], qf[u][7], kf[cur][4], kf[cur][6]);
            mma16816h(s2, s3, qf[u][0], qf[u][1], qf[u][2], qf[u][3], kf[cur][1], kf[cur][3]);
            mma16816h(s2, s3, qf[u][4], qf[u][5], qf[u][6], qf[u][7], kf[cur][5], kf[cur][7]);

            // exp2 directly on the f16 MMA output (log2 domain; no max)
            const uint32_t p0 = ex2h2(s0);
            const uint32_t p1 = ex2h2(s1);
            const uint32_t p2 = ex2h2(s2);
            const uint32_t p3 = ex2h2(s3);

            mma16816(o[u][0], p0, p1, p2, p3, vf[cur][0], vf[cur][1]);
            mma16816(o[u][1], p0, p1, p2, p3, vf[cur][2], vf[cur][3]);
            mma16816(o[u][2], p0, p1, p2, p3, vf[cur][4], vf[cur][5]);
            mma16816(o[u][3], p0, p1, p2, p3, vf[cur][6], vf[cur][7]);
            mma16816(ol[u], p0, p1, p2, p3, onesB, onesB);
        }
    }

#pragma unroll
    for (int u = 0; u < 2; ++u) {
        const int r0 = (wid * 2 + u) * 16;
        const float l0 = __shfl_sync(0xffffffffu, ol[u][0], lane & 28);
        const float l1 = __shfl_sync(0xffffffffu, ol[u][2], lane & 28);
        const float inv0 = 1.f / l0;
        const float inv1 = 1.f / l1;

        // epilogue: normalize + LePE conv (float2 weights) + half2 store
#pragma unroll
        for (int on = 0; on < 4; ++on) {
            const int d0 = on * 8 + tg2;
            const float2* wrow = &sW2[(d0 >> 1) * 9];
            const float2  b2   = sB2[d0 >> 1];
#pragma unroll
            for (int ocp = 0; ocp < 4; ocp += 2) {
                const int t  = r0 + g + ((ocp & 2) ? 8 : 0);
                const int ih = t >> 2;
                const int jw = t & 3;
                float a0 = b2.x, a1 = b2.y;
                const int ki0 = (ih == 0) ? 1 : 0;
                const int ki1 = (ih == 63) ? 2 : 3;
#pragma unroll
                for (int ki = 0; ki < 3; ++ki) {
                    if (ki < ki0 || ki >= ki1) continue;
                    const int ii = ih + ki - 1;
#pragma unroll
                    for (int kj = 0; kj < 3; ++kj) {
                        const int jj = jw + kj - 1;
                        if (jj < 0 || jj > 3) continue;
                        const __half2 vv = *reinterpret_cast<const __half2*>(
                            &sV[(ii * 4 + jj) * 40 + d0]);
                        const float2 vf2 = __half22float2(vv);
                        const float2 wv  = wrow[ki * 3 + kj];
                        a0 = fmaf(wv.x, vf2.x, a0);
                        a1 = fmaf(wv.y, vf2.y, a1);
                    }
                }
                const float inv = (ocp & 2) ? inv1 : inv0;
                const __half2 r = __floats2half2_rn(o[u][on][ocp] * inv + a0,
                                                    o[u][on][ocp + 1] * inv + a1);
                *reinterpret_cast<__half2*>(&og16[t * 32 + d0]) = r;
            }
        }
    }
}

// ---------------------------------------------------------------------------
// Kernel 3: scatter to (B,C,H,W).  grid = 8(b)*8(head)*8(h8) = 512
// ---------------------------------------------------------------------------
__global__ void __launch_bounds__(256)
scatter_kernel(float* __restrict__ out)
{
    extern __shared__ __half tileC[];  // [32 c][8 h][64 w]: c-stride 530, h-stride 66
    const int bid = blockIdx.x, tid = threadIdx.x;
    const int h8   = bid & 7;
    const int head = (bid >> 3) & 7;
    const int b    = bid >> 6;
    const int h0   = h8 * 8;
    const int lane = tid & 31, wid = tid >> 5;
    const int wb   = (b * 8 + head) * 16;
    const int d0   = (lane & 15) * 2;
    const int hiL  = lane >> 4;

    // phase 1: coalesced reads; shuffle-pair to build w-adjacent half2 of one
    // channel per lane, single STS.32
#pragma unroll
    for (int pp = wid; pp < 256; pp += 8) {
        const int p2 = pp * 2 + hiL;
        const int h = p2 >> 6, w = p2 & 63;
        const int win = wb + (w & 15);
        const int t   = (h0 + h) * 4 + (w >> 4);
        const uint32_t mine = *reinterpret_cast<const uint32_t*>(
            &g_o16[((size_t)win * 256 + t) * 32 + d0]);
        const uint32_t other = __shfl_xor_sync(0xffffffffu, mine, 16);
        uint32_t pairv;
        if (hiL == 0) {
            pairv = (mine & 0xFFFFu) | (other << 16);
        } else {
            pairv = (other >> 16) | (mine & 0xFFFF0000u);
        }
        const int c = d0 + hiL;
        const int weven = w & ~1;
        *reinterpret_cast<uint32_t*>(&tileC[c * 530 + h * 66 + weven]) = pairv;
    }
    __syncthreads();

    // phase 2: vectorized write, STG.128, 512B contiguous per warp
    const size_t ob = ((size_t)b * 256 + head * 32) * 4096 + (size_t)h0 * 64;
#pragma unroll
    for (int j = tid; j < 4096; j += 256) {
        const int w4 = j & 15, h = (j >> 4) & 7, c = j >> 7;
        const int sbase = c * 530 + h * 66 + w4 * 4;
        const float2 fa = __half22float2(*reinterpret_cast<const __half2*>(&tileC[sbase]));
        const float2 fb = __half22float2(*reinterpret_cast<const __half2*>(&tileC[sbase + 2]));
        float4 r;
        r.x = fa.x; r.y = fa.y; r.z = fb.x; r.w = fb.y;
        *reinterpret_cast<float4*>(&out[ob + (size_t)c * 4096 + h * 64 + w4 * 4]) = r;
    }
}

// ---------------------------------------------------------------------------
extern "C" void kernel_launch(void* const* d_in, const int* in_sizes, int n_in,
                              void* d_out, int out_size)
{
    (void)in_sizes; (void)n_in; (void)out_size;
    const float* temp = (const float*)d_in[0];
    const float* wgt  = (const float*)d_in[1];
    const float* bias = (const float*)d_in[2];
    float* out = (float*)d_out;

    cudaFuncSetAttribute(gather_kernel,  cudaFuncAttributeMaxDynamicSharedMemorySize, SMEM_A);
    cudaFuncSetAttribute(attn_kernel,    cudaFuncAttributeMaxDynamicSharedMemorySize, SMEM_B);
    cudaFuncSetAttribute(scatter_kernel, cudaFuncAttributeMaxDynamicSharedMemorySize, SMEM_C);

    gather_kernel<<<3072, 256, SMEM_A>>>(temp);
    attn_kernel<<<1024, 256, SMEM_B>>>(wgt, bias);
    scatter_kernel<<<512, 256, SMEM_C>>>(out);
}